// round 15
// baseline (speedup 1.0000x reference)
#include <cuda_runtime.h>

#define NBLK 128
#define NTHR 512
#define Bz   32
#define Ssz  2048
#define Isz  128
#define Hsz  512
#define Osz  128

#define PB_ZR0 32
#define PB_ZR1 5152
#define PB_G0  13344
#define PB_G1  15904
#define PB_Y   20000
#define OFF_W  20512
#define SMEM_FLOATS 40992
#define SMEM_BYTES (SMEM_FLOATS * 4)

// quad-interleaved k-major: idx(k,b) = (k>>2)*128 + 4b + (k&3)
__device__ float g_h0[2][Bz * Hsz];
__device__ float g_h1[2][Bz * Hsz];
__device__ float g_z0[Bz * Hsz];
__device__ float g_rh0[Bz * Hsz];
__device__ float g_z1[Bz * Hsz];
__device__ float g_rh1[Bz * Hsz];
__device__ float g_xT[(long long)Ssz * 128 * Bz];
__device__ unsigned g_count;

__device__ __forceinline__ int pidx(int k, int b) {
    return ((k >> 2) << 7) + (b << 2) + (k & 3);
}
__device__ __forceinline__ float4 ldcg128(const float* p) {
    float4 v;
    asm volatile("ld.global.cg.v4.f32 {%0,%1,%2,%3}, [%4];"
                 : "=f"(v.x), "=f"(v.y), "=f"(v.z), "=f"(v.w) : "l"(p));
    return v;
}
__device__ __forceinline__ float ldcgf(const float* p) {
    float v;
    asm volatile("ld.global.cg.f32 %0, [%1];" : "=f"(v) : "l"(p));
    return v;
}
__device__ __forceinline__ void stcgf(float* p, float v) {
    asm volatile("st.global.cg.f32 [%0], %1;" :: "l"(p), "f"(v));
}
__device__ __forceinline__ void bar_arrive() {
    __syncthreads();
    if (threadIdx.x == 0)
        asm volatile("red.release.gpu.add.u32 [%0], %1;"
                     :: "l"(&g_count), "r"(1u) : "memory");
}
__device__ __forceinline__ void bar_wait(unsigned target) {
    if (threadIdx.x == 0) {
        unsigned v;
        do {
            asm volatile("ld.acquire.gpu.u32 %0, [%1];"
                         : "=r"(v) : "l"(&g_count) : "memory");
        } while (v < target);
    }
    __syncthreads();
}
__device__ __forceinline__ float sigmoid_(float x) { return 1.0f / (1.0f + __expf(-x)); }
__device__ __forceinline__ float tanh_(float x)    { return 1.0f - 2.0f / (__expf(2.0f * x) + 1.0f); }
__device__ __forceinline__ unsigned long long f2(unsigned long long w,
                                                 unsigned long long s,
                                                 unsigned long long acc) {
    unsigned long long d;
    asm("fma.rn.f32x2 %0, %1, %2, %3;" : "=l"(d) : "l"(w), "l"(s), "l"(acc));
    return d;
}

__device__ __forceinline__ void burst8(float4* s4, const float* sg) {
#pragma unroll
    for (int p = 0; p < 8; ++p) s4[p] = ldcg128(sg + (p << 7));
}

// 4-accumulator partial reduce over N slots (stride 32 floats)
template <int N>
__device__ __forceinline__ float red4(const float* p, int b) {
    float a0 = 0.f, a1 = 0.f, a2 = 0.f, a3 = 0.f;
#pragma unroll
    for (int kq = 0; kq < N; kq += 4) {
        a0 += p[(kq + 0) * 32 + b];
        a1 += p[(kq + 1) * 32 + b];
        a2 += p[(kq + 2) * 32 + b];
        a3 += p[(kq + 3) * 32 + b];
    }
    return (a0 + a1) + (a2 + a3);
}

template <int R1, int R2, int R3>
__device__ __forceinline__ void dotc(const float4* __restrict__ s4,
                                     const float* __restrict__ wb1, int ws1,
                                     const float* __restrict__ wb2, int ws2,
                                     const float* __restrict__ wb3, int ws3,
                                     float* __restrict__ pd1, int prs1,
                                     float* __restrict__ pd2, int prs2,
                                     float* __restrict__ pd3, int prs3) {
    unsigned long long acc[R1 + R2 + R3];
#pragma unroll
    for (int i = 0; i < R1 + R2 + R3; ++i) acc[i] = 0ull;
#pragma unroll
    for (int p = 0; p < 8; ++p) {
        ulonglong2 sv = *(ulonglong2*)&s4[p];
#pragma unroll
        for (int r = 0; r < R1; ++r) {
            ulonglong2 wv = *(const ulonglong2*)(wb1 + r * ws1 + (p << 2));
            acc[r] = f2(wv.x, sv.x, acc[r]);
            acc[r] = f2(wv.y, sv.y, acc[r]);
        }
#pragma unroll
        for (int r = 0; r < R2; ++r) {
            ulonglong2 wv = *(const ulonglong2*)(wb2 + r * ws2 + (p << 2));
            acc[R1 + r] = f2(wv.x, sv.x, acc[R1 + r]);
            acc[R1 + r] = f2(wv.y, sv.y, acc[R1 + r]);
        }
#pragma unroll
        for (int r = 0; r < R3; ++r) {
            ulonglong2 wv = *(const ulonglong2*)(wb3 + r * ws3 + (p << 2));
            acc[R1 + R2 + r] = f2(wv.x, sv.x, acc[R1 + R2 + r]);
            acc[R1 + R2 + r] = f2(wv.y, sv.y, acc[R1 + R2 + r]);
        }
    }
#pragma unroll
    for (int r = 0; r < R1; ++r) { float2 a = *(float2*)&acc[r]; pd1[r * prs1] = a.x + a.y; }
#pragma unroll
    for (int r = 0; r < R2; ++r) { float2 a = *(float2*)&acc[R1 + r]; pd2[r * prs2] = a.x + a.y; }
#pragma unroll
    for (int r = 0; r < R3; ++r) { float2 a = *(float2*)&acc[R1 + R2 + r]; pd3[r * prs3] = a.x + a.y; }
}

template <int R1, int R2, int R3>
__device__ __forceinline__ void dotm3(const float* __restrict__ wb1, int ws1,
                                      const float* __restrict__ wb2, int ws2,
                                      const float* __restrict__ wb3, int ws3,
                                      const float* __restrict__ sg,
                                      float* __restrict__ pd1, int prs1,
                                      float* __restrict__ pd2, int prs2,
                                      float* __restrict__ pd3, int prs3) {
    float4 s4[8];
    burst8(s4, sg);
    dotc<R1, R2, R3>(s4, wb1, ws1, wb2, ws2, wb3, ws3, pd1, prs1, pd2, prs2, pd3, prs3);
}

__global__ void prep_k(const float* __restrict__ input) {
    long long idx = (long long)blockIdx.x * 1024 + threadIdx.x;
    if (idx == 0) g_count = 0u;
    if (idx < (long long)Bz * Ssz * Isz) {
        int b = (int)(idx >> 18);
        int rem = (int)(idx & 262143);
        int t = rem >> 7, k = rem & 127;
        g_xT[(long long)t * 4096 + pidx(k, b)] = input[idx];
    }
}

extern "C" __global__ void __launch_bounds__(NTHR, 1)
gru_r15(const float* __restrict__ input, const float* __restrict__ h0in,
        const float* __restrict__ Wx0, const float* __restrict__ Wh0,
        const float* __restrict__ bh0, const float* __restrict__ Wx1,
        const float* __restrict__ Wh1, const float* __restrict__ bh1,
        const float* __restrict__ Why, const float* __restrict__ bhy,
        float* __restrict__ out) {
    extern __shared__ float sm[];
    const int tid = threadIdx.x;
    const int bid = blockIdx.x;
    const int wid = tid >> 5, lane = tid & 31;

    float* bias = sm;
    float* pZR0 = sm + PB_ZR0;           // 8 x 20 (x:0-3, h:4-19)
    float* pZR1 = sm + PB_ZR1;           // 8 x 32 (h0:0-15, h1:16-31)
    float* pG0  = sm + PB_G0;            // 4 x 20 (x:0-3, h:4-19)
    float* pG1  = sm + PB_G1;            // 4 x 32 (x:0-15, rh1:16-31)
    float* pY   = sm + PB_Y;             // 1 x 16
    float* Wzr0 = sm + OFF_W;            // 8 x 640
    float* Wg0  = Wzr0 + 5120;           // 4 x 640
    float* Wzr1 = Wg0 + 2560;            // 8 x 1024
    float* Wg1  = Wzr1 + 8192;           // 4 x 1024
    float* Wy   = Wg1 + 4096;            // 1 x 512

    for (int i = tid; i < 8 * 640; i += NTHR) {
        int r = i / 640, k = i - r * 640, j = 8 * bid + r;
        Wzr0[i] = (k < Isz) ? Wx0[j * Isz + k] : Wh0[j * Hsz + k - Isz];
    }
    for (int i = tid; i < 4 * 640; i += NTHR) {
        int r = i / 640, k = i - r * 640, j = 2 * Hsz + 4 * bid + r;
        Wg0[i] = (k < Isz) ? Wx0[j * Isz + k] : Wh0[j * Hsz + k - Isz];
    }
    for (int i = tid; i < 8 * 1024; i += NTHR) {
        int r = i >> 10, k = i & 1023, j = 8 * bid + r;
        Wzr1[i] = (k < Hsz) ? Wx1[j * Hsz + k] : Wh1[j * Hsz + k - Hsz];
    }
    for (int i = tid; i < 4 * 1024; i += NTHR) {
        int r = i >> 10, k = i & 1023, j = 2 * Hsz + 4 * bid + r;
        Wg1[i] = (k < Hsz) ? Wx1[j * Hsz + k] : Wh1[j * Hsz + k - Hsz];
    }
    for (int i = tid; i < Hsz; i += NTHR) Wy[i] = Why[bid * Hsz + i];
    if (tid < 8)       bias[tid] = bh0[8 * bid + tid];
    else if (tid < 12) bias[tid] = bh0[2 * Hsz + 4 * bid + tid - 8];
    else if (tid < 20) bias[tid] = bh1[8 * bid + tid - 12];
    else if (tid < 24) bias[tid] = bh1[2 * Hsz + 4 * bid + tid - 20];
    else if (tid == 24) bias[tid] = bhy[bid];

    {
        int i = bid * NTHR + tid;
        if (i < Bz * 2 * Hsz) {
            int b = i >> 10, rest = i & 1023;
            float v = h0in[i];
            if (rest < Hsz) stcgf(&g_h0[0][pidx(rest, b)], v);
            else            stcgf(&g_h1[0][pidx(rest - Hsz, b)], v);
        }
    }
    __syncthreads();
    if (wid < 4) {   // tau=0 x dots
        int kq = wid;
        dotm3<8, 4, 0>(Wzr0 + kq * 32, 640, Wg0 + kq * 32, 640, Wg0, 640,
                       g_xT + kq * 1024 + 4 * lane,
                       pZR0 + kq * 32 + lane, 640,
                       pG0 + kq * 32 + lane, 640, pG0, 640);
    }
    unsigned bar = 0;
    bar_arrive(); bar_wait(++bar * NBLK);

    for (int tau = 0; tau <= Ssz; ++tau) {
        const int par = tau & 1;
        const int bn = (tau + 1) & 1;
        const float* h0c = g_h0[par];
        const float* h1o = g_h1[bn];

        // ======== W1: prefetch reduce operands, dual burst, dots ========
        float preh1 = 0.f;
        {
            int row = tid >> 5, b = tid & 31;
            if (row < 8) {
                int j = 8 * bid + row;
                if (j >= Hsz) preh1 = ldcgf(&h0c[pidx(j - Hsz, b)]);
            } else {
                int j = 8 * bid + (row - 8);
                if (j >= Hsz) preh1 = ldcgf(&h1o[pidx(j - Hsz, b)]);
            }
        }
        {
            int kq = wid;
            float4 sA[8], sB[8];
            burst8(sA, h0c + kq * 1024 + 4 * lane);
            burst8(sB, h1o + kq * 1024 + 4 * lane);
            dotc<8, 8, 4>(sA,
                          Wzr0 + Isz + kq * 32, 640,
                          Wzr1 + kq * 32, 1024,
                          Wg1 + kq * 32, 1024,
                          pZR0 + (4 + kq) * 32 + lane, 640,
                          pZR1 + kq * 32 + lane, 1024,
                          pG1 + kq * 32 + lane, 1024);
            dotc<8, 1, 0>(sB,
                          Wzr1 + 512 + kq * 32, 1024,
                          Wy + kq * 32, 512, Wy, 512,
                          pZR1 + (16 + kq) * 32 + lane, 1024,
                          pY + kq * 32 + lane, 1, pY + lane, 1);
        }
        __syncthreads();
        {
            int row = tid >> 5, b = tid & 31;
            if (row < 8) {
                if (tau < Ssz) {
                    float s = sigmoid_(bias[row] + red4<20>(pZR0 + row * 20 * 32, b));
                    int j = 8 * bid + row;
                    if (j < Hsz) stcgf(&g_z0[pidx(j, b)], s);
                    else         stcgf(&g_rh0[pidx(j - Hsz, b)], s * preh1);
                }
            } else {
                if (tau >= 1) {
                    int r2 = row - 8;
                    float s = sigmoid_(bias[12 + r2] + red4<32>(pZR1 + r2 * 32 * 32, b));
                    int j = 8 * bid + r2;
                    if (j < Hsz) stcgf(&g_z1[pidx(j, b)], s);
                    else         stcgf(&g_rh1[pidx(j - Hsz, b)], s * preh1);
                }
            }
        }
        bar_arrive(); bar_wait(++bar * NBLK);

        // ======== W2: prefetch z/h, dual burst, g-gate dots, y-output ========
        float prez = 0.f, preh2 = 0.f;
        if (tid < 256) {
            int row = tid >> 5, b = tid & 31;
            if (row < 4) {
                int u = 4 * bid + row;
                prez  = ldcgf(&g_z0[pidx(u, b)]);
                preh2 = ldcgf(&h0c[pidx(u, b)]);
            } else {
                int u = 4 * bid + (row - 4);
                prez  = ldcgf(&g_z1[pidx(u, b)]);
                preh2 = ldcgf(&h1o[pidx(u, b)]);
            }
        }
        {
            int kq = wid;
            float4 sA[8], sB[8];
            burst8(sA, g_rh0 + kq * 1024 + 4 * lane);
            burst8(sB, g_rh1 + kq * 1024 + 4 * lane);
            if (tau < Ssz)
                dotc<4, 0, 0>(sA, Wg0 + Isz + kq * 32, 640, Wg0, 640, Wg0, 640,
                              pG0 + (4 + kq) * 32 + lane, 640, pG0, 640, pG0, 640);
            if (tau >= 1)
                dotc<4, 0, 0>(sB, Wg1 + 512 + kq * 32, 1024, Wg1, 1024, Wg1, 1024,
                              pG1 + (16 + kq) * 32 + lane, 1024, pG1, 1024, pG1, 1024);
        }
        __syncthreads();
        if (tid < 256) {
            int row = tid >> 5, b = tid & 31;
            if (row < 4) {
                if (tau < Ssz) {
                    float g = tanh_(bias[8 + row] + red4<20>(pG0 + row * 20 * 32, b));
                    int u = 4 * bid + row;
                    stcgf(&g_h0[par ^ 1][pidx(u, b)], prez * preh2 + (1.f - prez) * g);
                }
            } else {
                if (tau >= 1) {
                    int r2 = row - 4;
                    float g = tanh_(bias[20 + r2] + red4<32>(pG1 + r2 * 32 * 32, b));
                    int u = 4 * bid + r2;
                    stcgf(&g_h1[tau & 1][pidx(u, b)], prez * preh2 + (1.f - prez) * g);
                }
            }
        } else if (tid < 288 && tau >= 2) {
            int b = tid - 256;
            float acc = bias[24] + red4<16>(pY, b);
            out[(b * Ssz + (tau - 2)) * Osz + bid] = acc;
        }
        bar_arrive();
        if (wid < 4 && tau + 1 < Ssz) {   // gap: next step's x dots
            int kq = wid;
            const float* xTn = g_xT + (long long)(tau + 1) * 4096;
            dotm3<8, 4, 0>(Wzr0 + kq * 32, 640, Wg0 + kq * 32, 640, Wg0, 640,
                           xTn + kq * 1024 + 4 * lane,
                           pZR0 + kq * 32 + lane, 640,
                           pG0 + kq * 32 + lane, 640, pG0, 640);
        }
        bar_wait(++bar * NBLK);
    }

    // ---------------- Epilogue ----------------
    if (tid < 32) {
        int b = tid;
        float acc = bias[24];
        for (int k = 0; k < Hsz; ++k)
            acc = fmaf(Wy[k], ldcgf(&g_h1[0][pidx(k, b)]), acc);
        out[(b * Ssz + (Ssz - 1)) * Osz + bid] = acc;
    }
    {
        int i = bid * NTHR + tid;
        if (i < Bz * 2 * Hsz) {
            int b = i >> 10, rest = i & 1023;
            float v = (rest < Hsz) ? ldcgf(&g_h0[0][pidx(rest, b)])
                                   : ldcgf(&g_h1[0][pidx(rest - Hsz, b)]);
            out[Bz * Ssz * Osz + i] = v;
        }
    }
}

extern "C" void kernel_launch(void* const* d_in, const int* in_sizes, int n_in,
                              void* d_out, int out_size) {
    cudaFuncSetAttribute(gru_r15,
                         cudaFuncAttributeMaxDynamicSharedMemorySize, SMEM_BYTES);
    prep_k<<<8192, 1024>>>((const float*)d_in[0]);
    gru_r15<<<NBLK, NTHR, SMEM_BYTES>>>(
        (const float*)d_in[0], (const float*)d_in[1], (const float*)d_in[2],
        (const float*)d_in[3], (const float*)d_in[4], (const float*)d_in[5],
        (const float*)d_in[6], (const float*)d_in[7], (const float*)d_in[8],
        (const float*)d_in[9], (float*)d_out);
}

// round 16
// speedup vs baseline: 1.0480x; 1.0480x over previous
#include <cuda_runtime.h>

#define NBLK 128
#define NTHR 512
#define Bz   32
#define Ssz  2048
#define Isz  128
#define Hsz  512
#define Osz  128

#define PB_ZR0 32
#define PB_ZR1 5152
#define PB_G0  13344
#define PB_G1  15904
#define PB_Y   20000
#define OFF_W  20512
#define SMEM_FLOATS 40992
#define SMEM_BYTES (SMEM_FLOATS * 4)

// quad-interleaved k-major: idx(k,b) = (k>>2)*128 + 4b + (k&3)
__device__ float g_h0[2][Bz * Hsz];
__device__ float g_h1[2][Bz * Hsz];
__device__ float g_z0[Bz * Hsz];
__device__ float g_rh0[Bz * Hsz];
__device__ float g_z1[Bz * Hsz];
__device__ float g_rh1[Bz * Hsz];
__device__ float g_xT[(long long)Ssz * 128 * Bz];
__device__ unsigned g_count;

__device__ __forceinline__ int pidx(int k, int b) {
    return ((k >> 2) << 7) + (b << 2) + (k & 3);
}
__device__ __forceinline__ float4 ldcg128(const float* p) {
    float4 v;
    asm volatile("ld.global.cg.v4.f32 {%0,%1,%2,%3}, [%4];"
                 : "=f"(v.x), "=f"(v.y), "=f"(v.z), "=f"(v.w) : "l"(p));
    return v;
}
__device__ __forceinline__ float ldcgf(const float* p) {
    float v;
    asm volatile("ld.global.cg.f32 %0, [%1];" : "=f"(v) : "l"(p));
    return v;
}
__device__ __forceinline__ void stcgf(float* p, float v) {
    asm volatile("st.global.cg.f32 [%0], %1;" :: "l"(p), "f"(v));
}
__device__ __forceinline__ void bar_arrive() {
    __syncthreads();
    if (threadIdx.x == 0)
        asm volatile("red.release.gpu.add.u32 [%0], %1;"
                     :: "l"(&g_count), "r"(1u) : "memory");
}
__device__ __forceinline__ void bar_wait(unsigned target) {
    if (threadIdx.x == 0) {
        unsigned v;
        do {
            asm volatile("ld.acquire.gpu.u32 %0, [%1];"
                         : "=r"(v) : "l"(&g_count) : "memory");
        } while (v < target);
    }
    __syncthreads();
}
__device__ __forceinline__ float sigmoid_(float x) { return 1.0f / (1.0f + __expf(-x)); }
__device__ __forceinline__ float tanh_(float x)    { return 1.0f - 2.0f / (__expf(2.0f * x) + 1.0f); }
__device__ __forceinline__ unsigned long long f2(unsigned long long w,
                                                 unsigned long long s,
                                                 unsigned long long acc) {
    unsigned long long d;
    asm("fma.rn.f32x2 %0, %1, %2, %3;" : "=l"(d) : "l"(w), "l"(s), "l"(acc));
    return d;
}

__device__ __forceinline__ void burst8(float4* s4, const float* sg) {
#pragma unroll
    for (int p = 0; p < 8; ++p) s4[p] = ldcg128(sg + (p << 7));
}

// 4-accumulator partial reduce over N slots (stride 32 floats)
template <int N>
__device__ __forceinline__ float red4(const float* p, int b) {
    float a0 = 0.f, a1 = 0.f, a2 = 0.f, a3 = 0.f;
#pragma unroll
    for (int kq = 0; kq < N; kq += 4) {
        a0 += p[(kq + 0) * 32 + b];
        a1 += p[(kq + 1) * 32 + b];
        a2 += p[(kq + 2) * 32 + b];
        a3 += p[(kq + 3) * 32 + b];
    }
    return (a0 + a1) + (a2 + a3);
}

template <int R1, int R2, int R3>
__device__ __forceinline__ void dotc(const float4* __restrict__ s4,
                                     const float* __restrict__ wb1, int ws1,
                                     const float* __restrict__ wb2, int ws2,
                                     const float* __restrict__ wb3, int ws3,
                                     float* __restrict__ pd1, int prs1,
                                     float* __restrict__ pd2, int prs2,
                                     float* __restrict__ pd3, int prs3) {
    unsigned long long acc[R1 + R2 + R3];
#pragma unroll
    for (int i = 0; i < R1 + R2 + R3; ++i) acc[i] = 0ull;
#pragma unroll
    for (int p = 0; p < 8; ++p) {
        ulonglong2 sv = *(ulonglong2*)&s4[p];
#pragma unroll
        for (int r = 0; r < R1; ++r) {
            ulonglong2 wv = *(const ulonglong2*)(wb1 + r * ws1 + (p << 2));
            acc[r] = f2(wv.x, sv.x, acc[r]);
            acc[r] = f2(wv.y, sv.y, acc[r]);
        }
#pragma unroll
        for (int r = 0; r < R2; ++r) {
            ulonglong2 wv = *(const ulonglong2*)(wb2 + r * ws2 + (p << 2));
            acc[R1 + r] = f2(wv.x, sv.x, acc[R1 + r]);
            acc[R1 + r] = f2(wv.y, sv.y, acc[R1 + r]);
        }
#pragma unroll
        for (int r = 0; r < R3; ++r) {
            ulonglong2 wv = *(const ulonglong2*)(wb3 + r * ws3 + (p << 2));
            acc[R1 + R2 + r] = f2(wv.x, sv.x, acc[R1 + R2 + r]);
            acc[R1 + R2 + r] = f2(wv.y, sv.y, acc[R1 + R2 + r]);
        }
    }
#pragma unroll
    for (int r = 0; r < R1; ++r) { float2 a = *(float2*)&acc[r]; pd1[r * prs1] = a.x + a.y; }
#pragma unroll
    for (int r = 0; r < R2; ++r) { float2 a = *(float2*)&acc[R1 + r]; pd2[r * prs2] = a.x + a.y; }
#pragma unroll
    for (int r = 0; r < R3; ++r) { float2 a = *(float2*)&acc[R1 + R2 + r]; pd3[r * prs3] = a.x + a.y; }
}

template <int R1, int R2, int R3>
__device__ __forceinline__ void dotm3(const float* __restrict__ wb1, int ws1,
                                      const float* __restrict__ wb2, int ws2,
                                      const float* __restrict__ wb3, int ws3,
                                      const float* __restrict__ sg,
                                      float* __restrict__ pd1, int prs1,
                                      float* __restrict__ pd2, int prs2,
                                      float* __restrict__ pd3, int prs3) {
    float4 s4[8];
    burst8(s4, sg);
    dotc<R1, R2, R3>(s4, wb1, ws1, wb2, ws2, wb3, ws3, pd1, prs1, pd2, prs2, pd3, prs3);
}

__global__ void prep_k(const float* __restrict__ input) {
    long long idx = (long long)blockIdx.x * 1024 + threadIdx.x;
    if (idx == 0) g_count = 0u;
    if (idx < (long long)Bz * Ssz * Isz) {
        int b = (int)(idx >> 18);
        int rem = (int)(idx & 262143);
        int t = rem >> 7, k = rem & 127;
        g_xT[(long long)t * 4096 + pidx(k, b)] = input[idx];
    }
}

extern "C" __global__ void __launch_bounds__(NTHR, 1)
gru_r16(const float* __restrict__ input, const float* __restrict__ h0in,
        const float* __restrict__ Wx0, const float* __restrict__ Wh0,
        const float* __restrict__ bh0, const float* __restrict__ Wx1,
        const float* __restrict__ Wh1, const float* __restrict__ bh1,
        const float* __restrict__ Why, const float* __restrict__ bhy,
        float* __restrict__ out) {
    extern __shared__ float sm[];
    const int tid = threadIdx.x;
    const int bid = blockIdx.x;
    const int wid = tid >> 5, lane = tid & 31;

    float* bias = sm;
    float* pZR0 = sm + PB_ZR0;           // 8 x 20 (x:0-3, h:4-19)
    float* pZR1 = sm + PB_ZR1;           // 8 x 32 (h0:0-15, h1:16-31)
    float* pG0  = sm + PB_G0;            // 4 x 20 (x:0-3, h:4-19)
    float* pG1  = sm + PB_G1;            // 4 x 32 (x:0-15, rh1:16-31)
    float* pY   = sm + PB_Y;             // 1 x 16
    float* Wzr0 = sm + OFF_W;            // 8 x 640
    float* Wg0  = Wzr0 + 5120;           // 4 x 640
    float* Wzr1 = Wg0 + 2560;            // 8 x 1024
    float* Wg1  = Wzr1 + 8192;           // 4 x 1024
    float* Wy   = Wg1 + 4096;            // 1 x 512

    for (int i = tid; i < 8 * 640; i += NTHR) {
        int r = i / 640, k = i - r * 640, j = 8 * bid + r;
        Wzr0[i] = (k < Isz) ? Wx0[j * Isz + k] : Wh0[j * Hsz + k - Isz];
    }
    for (int i = tid; i < 4 * 640; i += NTHR) {
        int r = i / 640, k = i - r * 640, j = 2 * Hsz + 4 * bid + r;
        Wg0[i] = (k < Isz) ? Wx0[j * Isz + k] : Wh0[j * Hsz + k - Isz];
    }
    for (int i = tid; i < 8 * 1024; i += NTHR) {
        int r = i >> 10, k = i & 1023, j = 8 * bid + r;
        Wzr1[i] = (k < Hsz) ? Wx1[j * Hsz + k] : Wh1[j * Hsz + k - Hsz];
    }
    for (int i = tid; i < 4 * 1024; i += NTHR) {
        int r = i >> 10, k = i & 1023, j = 2 * Hsz + 4 * bid + r;
        Wg1[i] = (k < Hsz) ? Wx1[j * Hsz + k] : Wh1[j * Hsz + k - Hsz];
    }
    for (int i = tid; i < Hsz; i += NTHR) Wy[i] = Why[bid * Hsz + i];
    if (tid < 8)       bias[tid] = bh0[8 * bid + tid];
    else if (tid < 12) bias[tid] = bh0[2 * Hsz + 4 * bid + tid - 8];
    else if (tid < 20) bias[tid] = bh1[8 * bid + tid - 12];
    else if (tid < 24) bias[tid] = bh1[2 * Hsz + 4 * bid + tid - 20];
    else if (tid == 24) bias[tid] = bhy[bid];

    {
        int i = bid * NTHR + tid;
        if (i < Bz * 2 * Hsz) {
            int b = i >> 10, rest = i & 1023;
            float v = h0in[i];
            if (rest < Hsz) stcgf(&g_h0[0][pidx(rest, b)], v);
            else            stcgf(&g_h1[0][pidx(rest - Hsz, b)], v);
        }
    }
    __syncthreads();
    if (wid < 4) {   // tau=0 x dots
        int kq = wid;
        dotm3<8, 4, 0>(Wzr0 + kq * 32, 640, Wg0 + kq * 32, 640, Wg0, 640,
                       g_xT + kq * 1024 + 4 * lane,
                       pZR0 + kq * 32 + lane, 640,
                       pG0 + kq * 32 + lane, 640, pG0, 640);
    }
    unsigned bar = 0;
    bar_arrive(); bar_wait(++bar * NBLK);

    for (int tau = 0; tau <= Ssz; ++tau) {
        const int par = tau & 1;
        const int bn = (tau + 1) & 1;
        const float* h0c = g_h0[par];
        const float* h1o = g_h1[bn];

        // ======== W1: prefetch reduce operands, dual burst, dots ========
        float preh1 = 0.f;
        {
            int row = tid >> 5, b = tid & 31;
            if (row < 8) {
                int j = 8 * bid + row;
                if (j >= Hsz) preh1 = ldcgf(&h0c[pidx(j - Hsz, b)]);
            } else {
                int j = 8 * bid + (row - 8);
                if (j >= Hsz) preh1 = ldcgf(&h1o[pidx(j - Hsz, b)]);
            }
        }
        {
            int kq = wid;
            float4 sA[8], sB[8];
            burst8(sA, h0c + kq * 1024 + 4 * lane);
            burst8(sB, h1o + kq * 1024 + 4 * lane);
            dotc<8, 8, 4>(sA,
                          Wzr0 + Isz + kq * 32, 640,
                          Wzr1 + kq * 32, 1024,
                          Wg1 + kq * 32, 1024,
                          pZR0 + (4 + kq) * 32 + lane, 640,
                          pZR1 + kq * 32 + lane, 1024,
                          pG1 + kq * 32 + lane, 1024);
            dotc<8, 1, 0>(sB,
                          Wzr1 + 512 + kq * 32, 1024,
                          Wy + kq * 32, 512, Wy, 512,
                          pZR1 + (16 + kq) * 32 + lane, 1024,
                          pY + kq * 32 + lane, 1, pY + lane, 1);
        }
        __syncthreads();
        {
            int row = tid >> 5, b = tid & 31;
            if (row < 8) {
                if (tau < Ssz) {
                    float s = sigmoid_(bias[row] + red4<20>(pZR0 + row * 20 * 32, b));
                    int j = 8 * bid + row;
                    if (j < Hsz) stcgf(&g_z0[pidx(j, b)], s);
                    else         stcgf(&g_rh0[pidx(j - Hsz, b)], s * preh1);
                }
            } else {
                if (tau >= 1) {
                    int r2 = row - 8;
                    float s = sigmoid_(bias[12 + r2] + red4<32>(pZR1 + r2 * 32 * 32, b));
                    int j = 8 * bid + r2;
                    if (j < Hsz) stcgf(&g_z1[pidx(j, b)], s);
                    else         stcgf(&g_rh1[pidx(j - Hsz, b)], s * preh1);
                }
            }
            if (tid < 32 && tau >= 2) {
                float acc = bias[24] + red4<16>(pY, tid);
                out[(tid * Ssz + (tau - 2)) * Osz + bid] = acc;
            }
        }
        bar_arrive(); bar_wait(++bar * NBLK);

        // ======== W2: prefetch z/h, sequential g-gate dots (R13 shape) ========
        float prez = 0.f, preh2 = 0.f;
        if (tid < 256) {
            int row = tid >> 5, b = tid & 31;
            if (row < 4) {
                int u = 4 * bid + row;
                prez  = ldcgf(&g_z0[pidx(u, b)]);
                preh2 = ldcgf(&h0c[pidx(u, b)]);
            } else {
                int u = 4 * bid + (row - 4);
                prez  = ldcgf(&g_z1[pidx(u, b)]);
                preh2 = ldcgf(&h1o[pidx(u, b)]);
            }
        }
        {
            int kq = wid;
            if (tau < Ssz)
                dotm3<4, 0, 0>(Wg0 + Isz + kq * 32, 640, Wg0, 640, Wg0, 640,
                               g_rh0 + kq * 1024 + 4 * lane,
                               pG0 + (4 + kq) * 32 + lane, 640,
                               pG0, 640, pG0, 640);
            if (tau >= 1)
                dotm3<4, 0, 0>(Wg1 + 512 + kq * 32, 1024, Wg1, 1024, Wg1, 1024,
                               g_rh1 + kq * 1024 + 4 * lane,
                               pG1 + (16 + kq) * 32 + lane, 1024,
                               pG1, 1024, pG1, 1024);
        }
        __syncthreads();
        if (tid < 256) {
            int row = tid >> 5, b = tid & 31;
            if (row < 4) {
                if (tau < Ssz) {
                    float g = tanh_(bias[8 + row] + red4<20>(pG0 + row * 20 * 32, b));
                    int u = 4 * bid + row;
                    stcgf(&g_h0[par ^ 1][pidx(u, b)], prez * preh2 + (1.f - prez) * g);
                }
            } else {
                if (tau >= 1) {
                    int r2 = row - 4;
                    float g = tanh_(bias[20 + r2] + red4<32>(pG1 + r2 * 32 * 32, b));
                    int u = 4 * bid + r2;
                    stcgf(&g_h1[tau & 1][pidx(u, b)], prez * preh2 + (1.f - prez) * g);
                }
            }
        }
        bar_arrive();
        if (wid < 4 && tau + 1 < Ssz) {   // gap: next step's x dots
            int kq = wid;
            const float* xTn = g_xT + (long long)(tau + 1) * 4096;
            dotm3<8, 4, 0>(Wzr0 + kq * 32, 640, Wg0 + kq * 32, 640, Wg0, 640,
                           xTn + kq * 1024 + 4 * lane,
                           pZR0 + kq * 32 + lane, 640,
                           pG0 + kq * 32 + lane, 640, pG0, 640);
        }
        bar_wait(++bar * NBLK);
    }

    // ---------------- Epilogue ----------------
    if (tid < 32) {
        int b = tid;
        float acc = bias[24];
        for (int k = 0; k < Hsz; ++k)
            acc = fmaf(Wy[k], ldcgf(&g_h1[0][pidx(k, b)]), acc);
        out[(b * Ssz + (Ssz - 1)) * Osz + bid] = acc;
    }
    {
        int i = bid * NTHR + tid;
        if (i < Bz * 2 * Hsz) {
            int b = i >> 10, rest = i & 1023;
            float v = (rest < Hsz) ? ldcgf(&g_h0[0][pidx(rest, b)])
                                   : ldcgf(&g_h1[0][pidx(rest - Hsz, b)]);
            out[Bz * Ssz * Osz + i] = v;
        }
    }
}

extern "C" void kernel_launch(void* const* d_in, const int* in_sizes, int n_in,
                              void* d_out, int out_size) {
    cudaFuncSetAttribute(gru_r16,
                         cudaFuncAttributeMaxDynamicSharedMemorySize, SMEM_BYTES);
    prep_k<<<8192, 1024>>>((const float*)d_in[0]);
    gru_r16<<<NBLK, NTHR, SMEM_BYTES>>>(
        (const float*)d_in[0], (const float*)d_in[1], (const float*)d_in[2],
        (const float*)d_in[3], (const float*)d_in[4], (const float*)d_in[5],
        (const float*)d_in[6], (const float*)d_in[7], (const float*)d_in[8],
        (const float*)d_in[9], (float*)d_out);
}

// round 17
// speedup vs baseline: 1.0600x; 1.0114x over previous
#include <cuda_runtime.h>

#define NBLK 128
#define NTHR 512
#define Bz   32
#define Ssz  2048
#define Isz  128
#define Hsz  512
#define Osz  128

#define PB_ZR0 32
#define PB_ZR1 6176
#define PB_G0  14368
#define PB_G1  16416
#define PB_Y   19488
#define OFF_W  20000
#define SMEM_FLOATS 40480
#define SMEM_BYTES (SMEM_FLOATS * 4)

// quad-interleaved k-major: idx(k,b) = (k>>2)*128 + 4b + (k&3)
__device__ float g_h0[2][Bz * Hsz];
__device__ float g_h1[2][Bz * Hsz];
__device__ float g_z0[Bz * Hsz];
__device__ float g_rh0[Bz * Hsz];
__device__ float g_z1[Bz * Hsz];
__device__ float g_rh1[Bz * Hsz];
__device__ float g_xT[(long long)Ssz * 128 * Bz];
__device__ unsigned g_count;

__device__ __forceinline__ int pidx(int k, int b) {
    return ((k >> 2) << 7) + (b << 2) + (k & 3);
}
__device__ __forceinline__ float4 ldcg128(const float* p) {
    float4 v;
    asm volatile("ld.global.cg.v4.f32 {%0,%1,%2,%3}, [%4];"
                 : "=f"(v.x), "=f"(v.y), "=f"(v.z), "=f"(v.w) : "l"(p));
    return v;
}
__device__ __forceinline__ float ldcgf(const float* p) {
    float v;
    asm volatile("ld.global.cg.f32 %0, [%1];" : "=f"(v) : "l"(p));
    return v;
}
__device__ __forceinline__ void stcgf(float* p, float v) {
    asm volatile("st.global.cg.f32 [%0], %1;" :: "l"(p), "f"(v));
}
__device__ __forceinline__ void bar_arrive() {
    __syncthreads();
    if (threadIdx.x == 0)
        asm volatile("red.release.gpu.add.u32 [%0], %1;"
                     :: "l"(&g_count), "r"(1u) : "memory");
}
__device__ __forceinline__ void bar_wait(unsigned target) {
    if (threadIdx.x == 0) {
        unsigned v;
        do {
            asm volatile("ld.acquire.gpu.u32 %0, [%1];"
                         : "=r"(v) : "l"(&g_count) : "memory");
        } while (v < target);
    }
    __syncthreads();
}
__device__ __forceinline__ float sigmoid_(float x) { return 1.0f / (1.0f + __expf(-x)); }
__device__ __forceinline__ float tanh_(float x)    { return 1.0f - 2.0f / (__expf(2.0f * x) + 1.0f); }
__device__ __forceinline__ unsigned long long f2(unsigned long long w,
                                                 unsigned long long s,
                                                 unsigned long long acc) {
    unsigned long long d;
    asm("fma.rn.f32x2 %0, %1, %2, %3;" : "=l"(d) : "l"(w), "l"(s), "l"(acc));
    return d;
}

template <int NP>
__device__ __forceinline__ void burstN(float4* s4, const float* sg) {
#pragma unroll
    for (int p = 0; p < NP; ++p) s4[p] = ldcg128(sg + (p << 7));
}

// 4-accumulator partial reduce over N slots (stride 32 floats)
template <int N>
__device__ __forceinline__ float red4(const float* p, int b) {
    float a0 = 0.f, a1 = 0.f, a2 = 0.f, a3 = 0.f;
#pragma unroll
    for (int kq = 0; kq < N; kq += 4) {
        a0 += p[(kq + 0) * 32 + b];
        a1 += p[(kq + 1) * 32 + b];
        a2 += p[(kq + 2) * 32 + b];
        a3 += p[(kq + 3) * 32 + b];
    }
    return (a0 + a1) + (a2 + a3);
}

template <int NP, int R1, int R2, int R3>
__device__ __forceinline__ void dotc(const float4* __restrict__ s4,
                                     const float* __restrict__ wb1, int ws1,
                                     const float* __restrict__ wb2, int ws2,
                                     const float* __restrict__ wb3, int ws3,
                                     float* __restrict__ pd1, int prs1,
                                     float* __restrict__ pd2, int prs2,
                                     float* __restrict__ pd3, int prs3) {
    unsigned long long acc[R1 + R2 + R3];
#pragma unroll
    for (int i = 0; i < R1 + R2 + R3; ++i) acc[i] = 0ull;
#pragma unroll
    for (int p = 0; p < NP; ++p) {
        ulonglong2 sv = *(ulonglong2*)&s4[p];
#pragma unroll
        for (int r = 0; r < R1; ++r) {
            ulonglong2 wv = *(const ulonglong2*)(wb1 + r * ws1 + (p << 2));
            acc[r] = f2(wv.x, sv.x, acc[r]);
            acc[r] = f2(wv.y, sv.y, acc[r]);
        }
#pragma unroll
        for (int r = 0; r < R2; ++r) {
            ulonglong2 wv = *(const ulonglong2*)(wb2 + r * ws2 + (p << 2));
            acc[R1 + r] = f2(wv.x, sv.x, acc[R1 + r]);
            acc[R1 + r] = f2(wv.y, sv.y, acc[R1 + r]);
        }
#pragma unroll
        for (int r = 0; r < R3; ++r) {
            ulonglong2 wv = *(const ulonglong2*)(wb3 + r * ws3 + (p << 2));
            acc[R1 + R2 + r] = f2(wv.x, sv.x, acc[R1 + R2 + r]);
            acc[R1 + R2 + r] = f2(wv.y, sv.y, acc[R1 + R2 + r]);
        }
    }
#pragma unroll
    for (int r = 0; r < R1; ++r) { float2 a = *(float2*)&acc[r]; pd1[r * prs1] = a.x + a.y; }
#pragma unroll
    for (int r = 0; r < R2; ++r) { float2 a = *(float2*)&acc[R1 + r]; pd2[r * prs2] = a.x + a.y; }
#pragma unroll
    for (int r = 0; r < R3; ++r) { float2 a = *(float2*)&acc[R1 + R2 + r]; pd3[r * prs3] = a.x + a.y; }
}

// gap x-dot: 16-k chunk (4 points), zr0-x 8 rows + g0-x 4 rows
__device__ __forceinline__ void xdots(const float* xT, const float* Wzr0,
                                      const float* Wg0, float* pZR0, float* pG0,
                                      int kq, int lane) {
    float4 s4[4];
    burstN<4>(s4, xT + kq * 512 + 4 * lane);
    dotc<4, 8, 4, 0>(s4, Wzr0 + kq * 16, 640, Wg0 + kq * 16, 640, Wg0, 640,
                     pZR0 + kq * 32 + lane, 768,
                     pG0 + kq * 32 + lane, 512, pG0, 512);
}

__global__ void prep_k(const float* __restrict__ input) {
    long long idx = (long long)blockIdx.x * 1024 + threadIdx.x;
    if (idx == 0) g_count = 0u;
    if (idx < (long long)Bz * Ssz * Isz) {
        int b = (int)(idx >> 18);
        int rem = (int)(idx & 262143);
        int t = rem >> 7, k = rem & 127;
        g_xT[(long long)t * 4096 + pidx(k, b)] = input[idx];
    }
}

extern "C" __global__ void __launch_bounds__(NTHR, 1)
gru_r17(const float* __restrict__ input, const float* __restrict__ h0in,
        const float* __restrict__ Wx0, const float* __restrict__ Wh0,
        const float* __restrict__ bh0, const float* __restrict__ Wx1,
        const float* __restrict__ Wh1, const float* __restrict__ bh1,
        const float* __restrict__ Why, const float* __restrict__ bhy,
        float* __restrict__ out) {
    extern __shared__ float sm[];
    const int tid = threadIdx.x;
    const int bid = blockIdx.x;
    const int wid = tid >> 5, lane = tid & 31;

    float* bias = sm;
    float* pZR0 = sm + PB_ZR0;           // 8 x 24 (x:0-7, h:8-23)
    float* pZR1 = sm + PB_ZR1;           // 8 x 32 (h0:0-15, h1:16-31)
    float* pG0  = sm + PB_G0;            // 4 x 16 (x:0-7, h:8-15)
    float* pG1  = sm + PB_G1;            // 4 x 24 (x:0-15, h:16-23)
    float* pY   = sm + PB_Y;             // 1 x 16
    float* Wzr0 = sm + OFF_W;            // 8 x 640
    float* Wg0  = Wzr0 + 5120;           // 4 x 640
    float* Wzr1 = Wg0 + 2560;            // 8 x 1024
    float* Wg1  = Wzr1 + 8192;           // 4 x 1024
    float* Wy   = Wg1 + 4096;            // 1 x 512

    for (int i = tid; i < 8 * 640; i += NTHR) {
        int r = i / 640, k = i - r * 640, j = 8 * bid + r;
        Wzr0[i] = (k < Isz) ? Wx0[j * Isz + k] : Wh0[j * Hsz + k - Isz];
    }
    for (int i = tid; i < 4 * 640; i += NTHR) {
        int r = i / 640, k = i - r * 640, j = 2 * Hsz + 4 * bid + r;
        Wg0[i] = (k < Isz) ? Wx0[j * Isz + k] : Wh0[j * Hsz + k - Isz];
    }
    for (int i = tid; i < 8 * 1024; i += NTHR) {
        int r = i >> 10, k = i & 1023, j = 8 * bid + r;
        Wzr1[i] = (k < Hsz) ? Wx1[j * Hsz + k] : Wh1[j * Hsz + k - Hsz];
    }
    for (int i = tid; i < 4 * 1024; i += NTHR) {
        int r = i >> 10, k = i & 1023, j = 2 * Hsz + 4 * bid + r;
        Wg1[i] = (k < Hsz) ? Wx1[j * Hsz + k] : Wh1[j * Hsz + k - Hsz];
    }
    for (int i = tid; i < Hsz; i += NTHR) Wy[i] = Why[bid * Hsz + i];
    if (tid < 8)       bias[tid] = bh0[8 * bid + tid];
    else if (tid < 12) bias[tid] = bh0[2 * Hsz + 4 * bid + tid - 8];
    else if (tid < 20) bias[tid] = bh1[8 * bid + tid - 12];
    else if (tid < 24) bias[tid] = bh1[2 * Hsz + 4 * bid + tid - 20];
    else if (tid == 24) bias[tid] = bhy[bid];

    {
        int i = bid * NTHR + tid;
        if (i < Bz * 2 * Hsz) {
            int b = i >> 10, rest = i & 1023;
            float v = h0in[i];
            if (rest < Hsz) stcgf(&g_h0[0][pidx(rest, b)], v);
            else            stcgf(&g_h1[0][pidx(rest - Hsz, b)], v);
        }
    }
    __syncthreads();
    if (wid < 8) xdots(g_xT, Wzr0, Wg0, pZR0, pG0, wid, lane);   // tau=0 x dots
    unsigned bar = 0;
    bar_arrive(); bar_wait(++bar * NBLK);

    for (int tau = 0; tau <= Ssz; ++tau) {
        const int par = tau & 1;
        const int bn = (tau + 1) & 1;
        const float* h0c = g_h0[par];
        const float* h1o = g_h1[bn];

        // ======== W1: prefetch reduce operands, dual burst, dots ========
        float preh1 = 0.f;
        {
            int row = tid >> 5, b = tid & 31;
            if (row < 8) {
                int j = 8 * bid + row;
                if (j >= Hsz) preh1 = ldcgf(&h0c[pidx(j - Hsz, b)]);
            } else {
                int j = 8 * bid + (row - 8);
                if (j >= Hsz) preh1 = ldcgf(&h1o[pidx(j - Hsz, b)]);
            }
        }
        {
            int kq = wid;
            float4 sA[8], sB[8];
            burstN<8>(sA, h0c + kq * 1024 + 4 * lane);
            burstN<8>(sB, h1o + kq * 1024 + 4 * lane);
            dotc<8, 8, 8, 4>(sA,
                             Wzr0 + Isz + kq * 32, 640,
                             Wzr1 + kq * 32, 1024,
                             Wg1 + kq * 32, 1024,
                             pZR0 + (8 + kq) * 32 + lane, 768,
                             pZR1 + kq * 32 + lane, 1024,
                             pG1 + kq * 32 + lane, 768);
            dotc<8, 8, 1, 0>(sB,
                             Wzr1 + 512 + kq * 32, 1024,
                             Wy + kq * 32, 512, Wy, 512,
                             pZR1 + (16 + kq) * 32 + lane, 1024,
                             pY + kq * 32 + lane, 1, pY + lane, 1);
        }
        __syncthreads();
        {
            int row = tid >> 5, b = tid & 31;
            if (row < 8) {
                if (tau < Ssz) {
                    float s = sigmoid_(bias[row] + red4<24>(pZR0 + row * 768, b));
                    int j = 8 * bid + row;
                    if (j < Hsz) stcgf(&g_z0[pidx(j, b)], s);
                    else         stcgf(&g_rh0[pidx(j - Hsz, b)], s * preh1);
                }
            } else {
                if (tau >= 1) {
                    int r2 = row - 8;
                    float s = sigmoid_(bias[12 + r2] + red4<32>(pZR1 + r2 * 1024, b));
                    int j = 8 * bid + r2;
                    if (j < Hsz) stcgf(&g_z1[pidx(j, b)], s);
                    else         stcgf(&g_rh1[pidx(j - Hsz, b)], s * preh1);
                }
            }
            if (tid < 32 && tau >= 2) {
                float acc = bias[24] + red4<16>(pY, tid);
                out[(tid * Ssz + (tau - 2)) * Osz + bid] = acc;
            }
        }
        bar_arrive(); bar_wait(++bar * NBLK);

        // ======== W2: prefetch z/h, single 64k job per warp ========
        float prez = 0.f, preh2 = 0.f;
        if (tid < 256) {
            int row = tid >> 5, b = tid & 31;
            if (row < 4) {
                int u = 4 * bid + row;
                prez  = ldcgf(&g_z0[pidx(u, b)]);
                preh2 = ldcgf(&h0c[pidx(u, b)]);
            } else {
                int u = 4 * bid + (row - 4);
                prez  = ldcgf(&g_z1[pidx(u, b)]);
                preh2 = ldcgf(&h1o[pidx(u, b)]);
            }
        }
        if (wid < 8) {
            if (tau < Ssz) {
                int kq = wid;   // rh0 64k chunk
                float4 s4[16];
                burstN<16>(s4, g_rh0 + kq * 2048 + 4 * lane);
                dotc<16, 4, 0, 0>(s4, Wg0 + Isz + kq * 64, 640, Wg0, 640, Wg0, 640,
                                  pG0 + (8 + kq) * 32 + lane, 512, pG0, 512, pG0, 512);
            }
        } else {
            if (tau >= 1) {
                int kq = wid - 8;   // rh1 64k chunk
                float4 s4[16];
                burstN<16>(s4, g_rh1 + kq * 2048 + 4 * lane);
                dotc<16, 4, 0, 0>(s4, Wg1 + 512 + kq * 64, 1024, Wg1, 1024, Wg1, 1024,
                                  pG1 + (16 + kq) * 32 + lane, 768, pG1, 768, pG1, 768);
            }
        }
        __syncthreads();
        if (tid < 256) {
            int row = tid >> 5, b = tid & 31;
            if (row < 4) {
                if (tau < Ssz) {
                    float g = tanh_(bias[8 + row] + red4<16>(pG0 + row * 512, b));
                    int u = 4 * bid + row;
                    stcgf(&g_h0[par ^ 1][pidx(u, b)], prez * preh2 + (1.f - prez) * g);
                }
            } else {
                if (tau >= 1) {
                    int r2 = row - 4;
                    float g = tanh_(bias[20 + r2] + red4<24>(pG1 + r2 * 768, b));
                    int u = 4 * bid + r2;
                    stcgf(&g_h1[tau & 1][pidx(u, b)], prez * preh2 + (1.f - prez) * g);
                }
            }
        }
        bar_arrive();
        if (wid < 8 && tau + 1 < Ssz) {   // gap: next step's x dots (8 warps)
            const float* xTn = g_xT + (long long)(tau + 1) * 4096;
            xdots(xTn, Wzr0, Wg0, pZR0, pG0, wid, lane);
        }
        bar_wait(++bar * NBLK);
    }

    // ---------------- Epilogue ----------------
    if (tid < 32) {
        int b = tid;
        float acc = bias[24];
        for (int k = 0; k < Hsz; ++k)
            acc = fmaf(Wy[k], ldcgf(&g_h1[0][pidx(k, b)]), acc);
        out[(b * Ssz + (Ssz - 1)) * Osz + bid] = acc;
    }
    {
        int i = bid * NTHR + tid;
        if (i < Bz * 2 * Hsz) {
            int b = i >> 10, rest = i & 1023;
            float v = (rest < Hsz) ? ldcgf(&g_h0[0][pidx(rest, b)])
                                   : ldcgf(&g_h1[0][pidx(rest - Hsz, b)]);
            out[Bz * Ssz * Osz + i] = v;
        }
    }
}

extern "C" void kernel_launch(void* const* d_in, const int* in_sizes, int n_in,
                              void* d_out, int out_size) {
    cudaFuncSetAttribute(gru_r17,
                         cudaFuncAttributeMaxDynamicSharedMemorySize, SMEM_BYTES);
    prep_k<<<8192, 1024>>>((const float*)d_in[0]);
    gru_r17<<<NBLK, NTHR, SMEM_BYTES>>>(
        (const float*)d_in[0], (const float*)d_in[1], (const float*)d_in[2],
        (const float*)d_in[3], (const float*)d_in[4], (const float*)d_in[5],
        (const float*)d_in[6], (const float*)d_in[7], (const float*)d_in[8],
        (const float*)d_in[9], (float*)d_out);
}